// round 4
// baseline (speedup 1.0000x reference)
#include <cuda_runtime.h>
#include <cstdint>

#define NNODES 100000
#define NEDGES 1600000
#define FIN    128
#define HID    64
#define NCLS   40

// ---------------- device scratch (allocation-free) ----------------
__device__ float g_deg[NNODES];
__device__ float g_dinv[NNODES];
__device__ float g_h1[(size_t)NNODES * HID];
__device__ float g_agg1[(size_t)NNODES * HID];
__device__ float g_h2[(size_t)NNODES * NCLS];

// ---------------- helpers ----------------
typedef unsigned long long u64;
__device__ __forceinline__ u64 ffma2(u64 a, u64 b, u64 c) {
    u64 d;
    asm("fma.rn.f32x2 %0, %1, %2, %3;" : "=l"(d) : "l"(a), "l"(b), "l"(c));
    return d;
}
__device__ __forceinline__ u64 pack2(float x) {
    u64 d;
    asm("mov.b64 %0, {%1, %1};" : "=l"(d) : "f"(x));
    return d;
}
union F2 { u64 u; float2 f; };
union W4 { float4 v; struct { u64 lo, hi; } u; };

__device__ __forceinline__ void red_add_v4(float* addr, float a, float b, float c, float d) {
    asm volatile("red.global.add.v4.f32 [%0], {%1, %2, %3, %4};"
                 :: "l"(addr), "f"(a), "f"(b), "f"(c), "f"(d)
                 : "memory");
}

// ---------------- degree / normalization ----------------
__global__ void k_init_deg() {
    int i = blockIdx.x * blockDim.x + threadIdx.x;
    if (i < NNODES) g_deg[i] = 1.0f;
}
__global__ void k_count_deg(const int* __restrict__ dst) {
    int e = blockIdx.x * blockDim.x + threadIdx.x;
    if (e < NEDGES) atomicAdd(&g_deg[dst[e]], 1.0f);
}
__global__ void k_dinv() {
    int i = blockIdx.x * blockDim.x + threadIdx.x;
    if (i < NNODES) g_dinv[i] = rsqrtf(g_deg[i]);
}

// ---------------- GEMM1: h1 = x @ W1 ; agg1 = h1*dinv^2 + b1 ----------------
// 256 threads, 128-row tile, thread = 4 rows x 8 cols via f32x2 FMA.
#define XS_PITCH 132
__global__ void __launch_bounds__(256) k_gemm1(const float* __restrict__ x,
                                               const float* __restrict__ W1,
                                               const float* __restrict__ b1) {
    __shared__ float xs[128 * XS_PITCH];  // 67.6 KB
    __shared__ float ws[FIN * HID];       // 32 KB
    const int tid  = threadIdx.x;
    const int row0 = blockIdx.x * 128;

    {
        const float4* wsrc = (const float4*)W1;
        float4* wdst = (float4*)ws;
        #pragma unroll
        for (int i = 0; i < 8; i++) wdst[tid + i * 256] = wsrc[tid + i * 256];
    }
    {
        #pragma unroll
        for (int i = 0; i < 16; i++) {
            int f = tid + i * 256;            // [0, 4096)
            int r = f >> 5;
            int o = (f & 31) << 2;
            float4 v = make_float4(0.f, 0.f, 0.f, 0.f);
            if (row0 + r < NNODES) v = *(const float4*)(x + (size_t)(row0 + r) * FIN + o);
            *(float4*)(xs + r * XS_PITCH + o) = v;
        }
    }
    __syncthreads();

    const int rp = tid >> 3;              // 0..31 -> rows rp*4..rp*4+3
    const int cg = tid & 7;               // 8 cols
    const float* wcol = ws + cg * 8;

    u64 acc[4][4];
    #pragma unroll
    for (int r = 0; r < 4; r++)
        #pragma unroll
        for (int j = 0; j < 4; j++) acc[r][j] = 0ull;

    const float* xr = xs + (rp * 4) * XS_PITCH;

    #pragma unroll 2
    for (int k = 0; k < FIN; k += 4) {
        float4 xa[4];
        #pragma unroll
        for (int r = 0; r < 4; r++)
            xa[r] = *(const float4*)(xr + r * XS_PITCH + k);
        #pragma unroll
        for (int kk = 0; kk < 4; kk++) {
            W4 w0, w1;
            w0.v = *(const float4*)(wcol + (k + kk) * HID);
            w1.v = *(const float4*)(wcol + (k + kk) * HID + 4);
            #pragma unroll
            for (int r = 0; r < 4; r++) {
                u64 xv = pack2((&xa[r].x)[kk]);
                acc[r][0] = ffma2(w0.u.lo, xv, acc[r][0]);
                acc[r][1] = ffma2(w0.u.hi, xv, acc[r][1]);
                acc[r][2] = ffma2(w1.u.lo, xv, acc[r][2]);
                acc[r][3] = ffma2(w1.u.hi, xv, acc[r][3]);
            }
        }
    }

    float4 bb0 = *(const float4*)(b1 + cg * 8);
    float4 bb1 = *(const float4*)(b1 + cg * 8 + 4);
    #pragma unroll
    for (int r = 0; r < 4; r++) {
        int row = row0 + rp * 4 + r;
        if (row >= NNODES) continue;
        float di = g_dinv[row];
        float dd = di * di;
        F2 a0, a1, a2, a3;
        a0.u = acc[r][0]; a1.u = acc[r][1]; a2.u = acc[r][2]; a3.u = acc[r][3];
        float4 o0 = make_float4(a0.f.x, a0.f.y, a1.f.x, a1.f.y);
        float4 o1 = make_float4(a2.f.x, a2.f.y, a3.f.x, a3.f.y);
        float* hp = g_h1 + (size_t)row * HID + cg * 8;
        *(float4*)(hp)     = o0;
        *(float4*)(hp + 4) = o1;
        float4 g0 = make_float4(fmaf(o0.x, dd, bb0.x), fmaf(o0.y, dd, bb0.y),
                                fmaf(o0.z, dd, bb0.z), fmaf(o0.w, dd, bb0.w));
        float4 g1 = make_float4(fmaf(o1.x, dd, bb1.x), fmaf(o1.y, dd, bb1.y),
                                fmaf(o1.z, dd, bb1.z), fmaf(o1.w, dd, bb1.w));
        float* ap = g_agg1 + (size_t)row * HID + cg * 8;
        *(float4*)(ap)     = g0;
        *(float4*)(ap + 4) = g1;
    }
}

// ---------------- scatter layer 1: one thread per edge, full 64-float row ----------------
__global__ void __launch_bounds__(256) k_scatter1(const int* __restrict__ src,
                                                  const int* __restrict__ dst) {
    int e = blockIdx.x * blockDim.x + threadIdx.x;
    if (e >= NEDGES) return;
    int s = src[e], d = dst[e];
    float norm = g_dinv[s] * g_dinv[d];
    const float4* hp = (const float4*)(g_h1 + (size_t)s * HID);
    float* ap = g_agg1 + (size_t)d * HID;
    float4 v[16];
    #pragma unroll
    for (int j = 0; j < 16; j++) v[j] = hp[j];
    #pragma unroll
    for (int j = 0; j < 16; j++)
        red_add_v4(ap + 4 * j,
                   v[j].x * norm, v[j].y * norm, v[j].z * norm, v[j].w * norm);
}

// ---------------- GEMM2: h2 = relu(agg1) @ W2 ; out = h2*dinv^2 + b2 ----------------
#define XS2_PITCH 68
__global__ void __launch_bounds__(256) k_gemm2(const float* __restrict__ W2,
                                               const float* __restrict__ b2,
                                               float* __restrict__ out) {
    __shared__ float xs[64 * XS2_PITCH];
    __shared__ float ws[HID * 64];
    const int tid  = threadIdx.x;
    const int row0 = blockIdx.x * 64;

    #pragma unroll
    for (int i = 0; i < 16; i++) {
        int idx = tid + i * 256;
        int k = idx >> 6, c = idx & 63;
        ws[idx] = (c < NCLS) ? W2[k * NCLS + c] : 0.0f;
    }
    #pragma unroll
    for (int i = 0; i < 4; i++) {
        int f = tid + i * 256;
        int r = f >> 4;
        int o = (f & 15) << 2;
        float4 v = make_float4(0.f, 0.f, 0.f, 0.f);
        if (row0 + r < NNODES) {
            float4 a = *(const float4*)(g_agg1 + (size_t)(row0 + r) * HID + o);
            v = make_float4(fmaxf(a.x, 0.f), fmaxf(a.y, 0.f),
                            fmaxf(a.z, 0.f), fmaxf(a.w, 0.f));
        }
        *(float4*)(xs + r * XS2_PITCH + o) = v;
    }
    __syncthreads();

    const int rp = tid >> 3;
    const int cg = tid & 7;
    if (cg >= 5) return;                  // cols 40..63 are padding
    const int r0 = rp * 2;
    const float* xr0 = xs + r0 * XS2_PITCH;
    const float* xr1 = xs + (r0 + 1) * XS2_PITCH;
    const float* wcol = ws + cg * 8;

    u64 acc[2][4];
    #pragma unroll
    for (int r = 0; r < 2; r++)
        #pragma unroll
        for (int j = 0; j < 4; j++) acc[r][j] = 0ull;

    #pragma unroll 4
    for (int k = 0; k < HID; k += 4) {
        float4 xa = *(const float4*)(xr0 + k);
        float4 xb = *(const float4*)(xr1 + k);
        #pragma unroll
        for (int kk = 0; kk < 4; kk++) {
            u64 xa2 = pack2((&xa.x)[kk]);
            u64 xb2 = pack2((&xb.x)[kk]);
            W4 w0, w1;
            w0.v = *(const float4*)(wcol + (k + kk) * 64);
            w1.v = *(const float4*)(wcol + (k + kk) * 64 + 4);
            acc[0][0] = ffma2(w0.u.lo, xa2, acc[0][0]);
            acc[0][1] = ffma2(w0.u.hi, xa2, acc[0][1]);
            acc[0][2] = ffma2(w1.u.lo, xa2, acc[0][2]);
            acc[0][3] = ffma2(w1.u.hi, xa2, acc[0][3]);
            acc[1][0] = ffma2(w0.u.lo, xb2, acc[1][0]);
            acc[1][1] = ffma2(w0.u.hi, xb2, acc[1][1]);
            acc[1][2] = ffma2(w1.u.lo, xb2, acc[1][2]);
            acc[1][3] = ffma2(w1.u.hi, xb2, acc[1][3]);
        }
    }

    float4 bb0 = *(const float4*)(b2 + cg * 8);
    float4 bb1 = *(const float4*)(b2 + cg * 8 + 4);
    #pragma unroll
    for (int r = 0; r < 2; r++) {
        int row = row0 + r0 + r;
        if (row >= NNODES) continue;
        float di = g_dinv[row];
        float dd = di * di;
        F2 a0, a1, a2, a3;
        a0.u = acc[r][0]; a1.u = acc[r][1]; a2.u = acc[r][2]; a3.u = acc[r][3];
        float4 o0 = make_float4(a0.f.x, a0.f.y, a1.f.x, a1.f.y);
        float4 o1 = make_float4(a2.f.x, a2.f.y, a3.f.x, a3.f.y);
        float* hp = g_h2 + (size_t)row * NCLS + cg * 8;
        *(float4*)(hp)     = o0;
        *(float4*)(hp + 4) = o1;
        float4 g0 = make_float4(fmaf(o0.x, dd, bb0.x), fmaf(o0.y, dd, bb0.y),
                                fmaf(o0.z, dd, bb0.z), fmaf(o0.w, dd, bb0.w));
        float4 g1 = make_float4(fmaf(o1.x, dd, bb1.x), fmaf(o1.y, dd, bb1.y),
                                fmaf(o1.z, dd, bb1.z), fmaf(o1.w, dd, bb1.w));
        float* op = out + (size_t)row * NCLS + cg * 8;
        *(float4*)(op)     = g0;
        *(float4*)(op + 4) = g1;
    }
}

// ---------------- scatter layer 2: one thread per edge, full 40-float row ----------------
__global__ void __launch_bounds__(256) k_scatter2(const int* __restrict__ src,
                                                  const int* __restrict__ dst,
                                                  float* __restrict__ out) {
    int e = blockIdx.x * blockDim.x + threadIdx.x;
    if (e >= NEDGES) return;
    int s = src[e], d = dst[e];
    float norm = g_dinv[s] * g_dinv[d];
    const float4* hp = (const float4*)(g_h2 + (size_t)s * NCLS);
    float* op = out + (size_t)d * NCLS;
    float4 v[10];
    #pragma unroll
    for (int j = 0; j < 10; j++) v[j] = hp[j];
    #pragma unroll
    for (int j = 0; j < 10; j++)
        red_add_v4(op + 4 * j,
                   v[j].x * norm, v[j].y * norm, v[j].z * norm, v[j].w * norm);
}

// ---------------- launch ----------------
extern "C" void kernel_launch(void* const* d_in, const int* in_sizes, int n_in,
                              void* d_out, int out_size) {
    const float* x   = (const float*)d_in[0];
    const int*   ei  = (const int*)d_in[1];
    const float* W1  = (const float*)d_in[2];
    const float* b1  = (const float*)d_in[3];
    const float* W2  = (const float*)d_in[4];
    const float* b2  = (const float*)d_in[5];
    float* out = (float*)d_out;

    const int* src = ei;
    const int* dst = ei + NEDGES;

    k_init_deg<<<(NNODES + 255) / 256, 256>>>();
    k_count_deg<<<(NEDGES + 255) / 256, 256>>>(dst);
    k_dinv<<<(NNODES + 255) / 256, 256>>>();

    k_gemm1<<<(NNODES + 127) / 128, 256>>>(x, W1, b1);
    k_scatter1<<<(NEDGES + 255) / 256, 256>>>(src, dst);

    k_gemm2<<<(NNODES + 63) / 64, 256>>>(W2, b2, out);
    k_scatter2<<<(NEDGES + 255) / 256, 256>>>(src, dst, out);
}

// round 5
// speedup vs baseline: 1.4867x; 1.4867x over previous
#include <cuda_runtime.h>
#include <cstdint>

#define NNODES 100000
#define NEDGES 1600000
#define FIN    128
#define HID    64
#define NCLS   40

// ---------------- device scratch (allocation-free) ----------------
__device__ float g_deg[NNODES];
__device__ float g_dinv[NNODES];
__device__ float g_h1[(size_t)NNODES * HID];     // (x @ W1) * dinv[row]  (pre-scaled)
__device__ float g_agg1[(size_t)NNODES * HID];   // layer-1 agg (self-loop + bias folded)
__device__ float g_h2[(size_t)NNODES * NCLS];    // (relu(agg1) @ W2) * dinv[row]

// ---------------- helpers ----------------
typedef unsigned long long u64;
__device__ __forceinline__ u64 ffma2(u64 a, u64 b, u64 c) {
    u64 d;
    asm("fma.rn.f32x2 %0, %1, %2, %3;" : "=l"(d) : "l"(a), "l"(b), "l"(c));
    return d;
}
__device__ __forceinline__ u64 pack2(float x) {
    u64 d;
    asm("mov.b64 %0, {%1, %1};" : "=l"(d) : "f"(x));
    return d;
}
union F2 { u64 u; float2 f; };
union W4 { float4 v; struct { u64 lo, hi; } u; };

__device__ __forceinline__ void red_add_v4(float* addr, float a, float b, float c, float d) {
    asm volatile("red.global.add.v4.f32 [%0], {%1, %2, %3, %4};"
                 :: "l"(addr), "f"(a), "f"(b), "f"(c), "f"(d)
                 : "memory");
}

// ---------------- degree / normalization ----------------
__global__ void k_init_deg() {
    int i = blockIdx.x * blockDim.x + threadIdx.x;
    if (i < NNODES) g_deg[i] = 1.0f;
}
__global__ void k_count_deg(const int* __restrict__ dst) {
    int e = blockIdx.x * blockDim.x + threadIdx.x;
    if (e < NEDGES) atomicAdd(&g_deg[dst[e]], 1.0f);
}
__global__ void k_dinv() {
    int i = blockIdx.x * blockDim.x + threadIdx.x;
    if (i < NNODES) g_dinv[i] = rsqrtf(g_deg[i]);
}

// ---------------- GEMM1: h1s = (x @ W1)*dinv ; agg1 = h1s*dinv + b1 ----------------
// 256 threads, 128-row tile, thread = 4 rows x 8 cols via f32x2 FMA.
#define XS_PITCH 132
__global__ void __launch_bounds__(256) k_gemm1(const float* __restrict__ x,
                                               const float* __restrict__ W1,
                                               const float* __restrict__ b1) {
    __shared__ float xs[128 * XS_PITCH];  // 67.6 KB
    __shared__ float ws[FIN * HID];       // 32 KB
    const int tid  = threadIdx.x;
    const int row0 = blockIdx.x * 128;

    {
        const float4* wsrc = (const float4*)W1;
        float4* wdst = (float4*)ws;
        #pragma unroll
        for (int i = 0; i < 8; i++) wdst[tid + i * 256] = wsrc[tid + i * 256];
    }
    {
        #pragma unroll
        for (int i = 0; i < 16; i++) {
            int f = tid + i * 256;            // [0, 4096)
            int r = f >> 5;
            int o = (f & 31) << 2;
            float4 v = make_float4(0.f, 0.f, 0.f, 0.f);
            if (row0 + r < NNODES) v = *(const float4*)(x + (size_t)(row0 + r) * FIN + o);
            *(float4*)(xs + r * XS_PITCH + o) = v;
        }
    }
    __syncthreads();

    const int rp = tid >> 3;              // rows rp*4..rp*4+3
    const int cg = tid & 7;               // 8-col group
    const float* wcol = ws + cg * 8;

    u64 acc[4][4];
    #pragma unroll
    for (int r = 0; r < 4; r++)
        #pragma unroll
        for (int j = 0; j < 4; j++) acc[r][j] = 0ull;

    const float* xr = xs + (rp * 4) * XS_PITCH;

    #pragma unroll 2
    for (int k = 0; k < FIN; k += 4) {
        float4 xa[4];
        #pragma unroll
        for (int r = 0; r < 4; r++)
            xa[r] = *(const float4*)(xr + r * XS_PITCH + k);
        #pragma unroll
        for (int kk = 0; kk < 4; kk++) {
            W4 w0, w1;
            w0.v = *(const float4*)(wcol + (k + kk) * HID);
            w1.v = *(const float4*)(wcol + (k + kk) * HID + 4);
            #pragma unroll
            for (int r = 0; r < 4; r++) {
                u64 xv = pack2((&xa[r].x)[kk]);
                acc[r][0] = ffma2(w0.u.lo, xv, acc[r][0]);
                acc[r][1] = ffma2(w0.u.hi, xv, acc[r][1]);
                acc[r][2] = ffma2(w1.u.lo, xv, acc[r][2]);
                acc[r][3] = ffma2(w1.u.hi, xv, acc[r][3]);
            }
        }
    }

    float4 bb0 = *(const float4*)(b1 + cg * 8);
    float4 bb1 = *(const float4*)(b1 + cg * 8 + 4);
    #pragma unroll
    for (int r = 0; r < 4; r++) {
        int row = row0 + rp * 4 + r;
        if (row >= NNODES) continue;
        float di = g_dinv[row];
        F2 a0, a1, a2, a3;
        a0.u = acc[r][0]; a1.u = acc[r][1]; a2.u = acc[r][2]; a3.u = acc[r][3];
        // pre-scaled h1: h1s = h1 * dinv[row]
        float4 o0 = make_float4(a0.f.x * di, a0.f.y * di, a1.f.x * di, a1.f.y * di);
        float4 o1 = make_float4(a2.f.x * di, a2.f.y * di, a3.f.x * di, a3.f.y * di);
        float* hp = g_h1 + (size_t)row * HID + cg * 8;
        *(float4*)(hp)     = o0;
        *(float4*)(hp + 4) = o1;
        // agg1 init: self-loop = h1s * dinv + b1
        float4 g0 = make_float4(fmaf(o0.x, di, bb0.x), fmaf(o0.y, di, bb0.y),
                                fmaf(o0.z, di, bb0.z), fmaf(o0.w, di, bb0.w));
        float4 g1 = make_float4(fmaf(o1.x, di, bb1.x), fmaf(o1.y, di, bb1.y),
                                fmaf(o1.z, di, bb1.z), fmaf(o1.w, di, bb1.w));
        float* ap = g_agg1 + (size_t)row * HID + cg * 8;
        *(float4*)(ap)     = g0;
        *(float4*)(ap + 4) = g1;
    }
}

// ---------------- scatter layer 1: agg1[dst] += h1s[src]*dinv[dst] ----------------
// 16 lanes per edge (lane j owns float4 chunk j) — coalesced gather + reduce.
__global__ void k_scatter1(const int* __restrict__ src, const int* __restrict__ dst) {
    long long t = (long long)blockIdx.x * blockDim.x + threadIdx.x;
    if (t >= (long long)NEDGES * 16) return;
    int e = (int)(t >> 4);
    int g = (int)(t & 15);
    int s = src[e], d = dst[e];
    float norm = g_dinv[d];                       // h1s already has dinv[src]
    float4 v = *(const float4*)(g_h1 + (size_t)s * HID + g * 4);
    red_add_v4(g_agg1 + (size_t)d * HID + g * 4,
               v.x * norm, v.y * norm, v.z * norm, v.w * norm);
}

// ---------------- GEMM2: h2s = (relu(agg1) @ W2)*dinv ; out = h2s*dinv + b2 ----------------
#define XS2_PITCH 68
__global__ void __launch_bounds__(256) k_gemm2(const float* __restrict__ W2,
                                               const float* __restrict__ b2,
                                               float* __restrict__ out) {
    __shared__ float xs[64 * XS2_PITCH];
    __shared__ float ws[HID * 64];
    const int tid  = threadIdx.x;
    const int row0 = blockIdx.x * 64;

    #pragma unroll
    for (int i = 0; i < 16; i++) {
        int idx = tid + i * 256;
        int k = idx >> 6, c = idx & 63;
        ws[idx] = (c < NCLS) ? W2[k * NCLS + c] : 0.0f;
    }
    #pragma unroll
    for (int i = 0; i < 4; i++) {
        int f = tid + i * 256;
        int r = f >> 4;
        int o = (f & 15) << 2;
        float4 v = make_float4(0.f, 0.f, 0.f, 0.f);
        if (row0 + r < NNODES) {
            float4 a = *(const float4*)(g_agg1 + (size_t)(row0 + r) * HID + o);
            v = make_float4(fmaxf(a.x, 0.f), fmaxf(a.y, 0.f),
                            fmaxf(a.z, 0.f), fmaxf(a.w, 0.f));
        }
        *(float4*)(xs + r * XS2_PITCH + o) = v;
    }
    __syncthreads();

    const int rp = tid >> 3;
    const int cg = tid & 7;
    if (cg >= 5) return;                  // cols 40..63 are padding
    const int r0 = rp * 2;
    const float* xr0 = xs + r0 * XS2_PITCH;
    const float* xr1 = xs + (r0 + 1) * XS2_PITCH;
    const float* wcol = ws + cg * 8;

    u64 acc[2][4];
    #pragma unroll
    for (int r = 0; r < 2; r++)
        #pragma unroll
        for (int j = 0; j < 4; j++) acc[r][j] = 0ull;

    #pragma unroll 4
    for (int k = 0; k < HID; k += 4) {
        float4 xa = *(const float4*)(xr0 + k);
        float4 xb = *(const float4*)(xr1 + k);
        #pragma unroll
        for (int kk = 0; kk < 4; kk++) {
            u64 xa2 = pack2((&xa.x)[kk]);
            u64 xb2 = pack2((&xb.x)[kk]);
            W4 w0, w1;
            w0.v = *(const float4*)(wcol + (k + kk) * 64);
            w1.v = *(const float4*)(wcol + (k + kk) * 64 + 4);
            acc[0][0] = ffma2(w0.u.lo, xa2, acc[0][0]);
            acc[0][1] = ffma2(w0.u.hi, xa2, acc[0][1]);
            acc[0][2] = ffma2(w1.u.lo, xa2, acc[0][2]);
            acc[0][3] = ffma2(w1.u.hi, xa2, acc[0][3]);
            acc[1][0] = ffma2(w0.u.lo, xb2, acc[1][0]);
            acc[1][1] = ffma2(w0.u.hi, xb2, acc[1][1]);
            acc[1][2] = ffma2(w1.u.lo, xb2, acc[1][2]);
            acc[1][3] = ffma2(w1.u.hi, xb2, acc[1][3]);
        }
    }

    float4 bb0 = *(const float4*)(b2 + cg * 8);
    float4 bb1 = *(const float4*)(b2 + cg * 8 + 4);
    #pragma unroll
    for (int r = 0; r < 2; r++) {
        int row = row0 + r0 + r;
        if (row >= NNODES) continue;
        float di = g_dinv[row];
        F2 a0, a1, a2, a3;
        a0.u = acc[r][0]; a1.u = acc[r][1]; a2.u = acc[r][2]; a3.u = acc[r][3];
        // pre-scaled h2: h2s = h2 * dinv[row]
        float4 o0 = make_float4(a0.f.x * di, a0.f.y * di, a1.f.x * di, a1.f.y * di);
        float4 o1 = make_float4(a2.f.x * di, a2.f.y * di, a3.f.x * di, a3.f.y * di);
        float* hp = g_h2 + (size_t)row * NCLS + cg * 8;
        *(float4*)(hp)     = o0;
        *(float4*)(hp + 4) = o1;
        // out init: self-loop = h2s * dinv + b2
        float4 g0 = make_float4(fmaf(o0.x, di, bb0.x), fmaf(o0.y, di, bb0.y),
                                fmaf(o0.z, di, bb0.z), fmaf(o0.w, di, bb0.w));
        float4 g1 = make_float4(fmaf(o1.x, di, bb1.x), fmaf(o1.y, di, bb1.y),
                                fmaf(o1.z, di, bb1.z), fmaf(o1.w, di, bb1.w));
        float* op = out + (size_t)row * NCLS + cg * 8;
        *(float4*)(op)     = g0;
        *(float4*)(op + 4) = g1;
    }
}

// ---------------- scatter layer 2: out[dst] += h2s[src]*dinv[dst] ----------------
// 10 float4 groups per edge.
__global__ void k_scatter2(const int* __restrict__ src, const int* __restrict__ dst,
                           float* __restrict__ out) {
    long long t = (long long)blockIdx.x * blockDim.x + threadIdx.x;
    if (t >= (long long)NEDGES * 10) return;
    int e = (int)(t / 10);
    int g = (int)(t - (long long)e * 10);
    int s = src[e], d = dst[e];
    float norm = g_dinv[d];                       // h2s already has dinv[src]
    float4 v = *(const float4*)(g_h2 + (size_t)s * NCLS + g * 4);
    red_add_v4(out + (size_t)d * NCLS + g * 4,
               v.x * norm, v.y * norm, v.z * norm, v.w * norm);
}

// ---------------- launch ----------------
extern "C" void kernel_launch(void* const* d_in, const int* in_sizes, int n_in,
                              void* d_out, int out_size) {
    const float* x   = (const float*)d_in[0];
    const int*   ei  = (const int*)d_in[1];
    const float* W1  = (const float*)d_in[2];
    const float* b1  = (const float*)d_in[3];
    const float* W2  = (const float*)d_in[4];
    const float* b2  = (const float*)d_in[5];
    float* out = (float*)d_out;

    const int* src = ei;
    const int* dst = ei + NEDGES;

    k_init_deg<<<(NNODES + 255) / 256, 256>>>();
    k_count_deg<<<(NEDGES + 255) / 256, 256>>>(dst);
    k_dinv<<<(NNODES + 255) / 256, 256>>>();

    k_gemm1<<<(NNODES + 127) / 128, 256>>>(x, W1, b1);
    {
        long long tot = (long long)NEDGES * 16;
        k_scatter1<<<(unsigned)((tot + 255) / 256), 256>>>(src, dst);
    }
    k_gemm2<<<(NNODES + 63) / 64, 256>>>(W2, b2, out);
    {
        long long tot = (long long)NEDGES * 10;
        k_scatter2<<<(unsigned)((tot + 255) / 256), 256>>>(src, dst, out);
    }
}

// round 6
// speedup vs baseline: 1.5507x; 1.0430x over previous
#include <cuda_runtime.h>
#include <cstdint>

#define NNODES 100000
#define NEDGES 1600000
#define FIN    128
#define HID    64
#define NCLS   40

// ---------------- device scratch (allocation-free) ----------------
__device__ float g_deg[NNODES];
__device__ float g_dinv[NNODES];
__device__ float g_h1[(size_t)NNODES * HID];     // (x @ W1) * dinv[row]  (pre-scaled)
__device__ float g_agg1[(size_t)NNODES * HID];   // layer-1 agg (self-loop + bias folded)
__device__ float g_h2[(size_t)NNODES * NCLS];    // (relu(agg1) @ W2) * dinv[row]

// ---------------- helpers ----------------
typedef unsigned long long u64;
__device__ __forceinline__ u64 ffma2(u64 a, u64 b, u64 c) {
    u64 d;
    asm("fma.rn.f32x2 %0, %1, %2, %3;" : "=l"(d) : "l"(a), "l"(b), "l"(c));
    return d;
}
__device__ __forceinline__ u64 pack2(float x) {
    u64 d;
    asm("mov.b64 %0, {%1, %1};" : "=l"(d) : "f"(x));
    return d;
}
union F2 { u64 u; float2 f; };
union W4 { float4 v; struct { u64 lo, hi; } u; };

__device__ __forceinline__ void red_add_v4(float* addr, float a, float b, float c, float d) {
    asm volatile("red.global.add.v4.f32 [%0], {%1, %2, %3, %4};"
                 :: "l"(addr), "f"(a), "f"(b), "f"(c), "f"(d)
                 : "memory");
}

// ---------------- degree / normalization ----------------
__global__ void k_init_deg() {
    int i = blockIdx.x * blockDim.x + threadIdx.x;
    if (i < NNODES) g_deg[i] = 1.0f;
}
__global__ void k_count_deg(const int* __restrict__ dst) {
    int e = blockIdx.x * blockDim.x + threadIdx.x;
    if (e < NEDGES) atomicAdd(&g_deg[dst[e]], 1.0f);
}
__global__ void k_dinv() {
    int i = blockIdx.x * blockDim.x + threadIdx.x;
    if (i < NNODES) g_dinv[i] = rsqrtf(g_deg[i]);
}

// ---------------- GEMM1: h1s = (x @ W1)*dinv ; agg1 = h1s*dinv + b1 ----------------
// 128 threads, 128-row tile, thread = 8 rows x 8 cols via f32x2 FMA (32 accumulators).
#define XS_PITCH 132
__global__ void __launch_bounds__(128, 2) k_gemm1(const float* __restrict__ x,
                                                  const float* __restrict__ W1,
                                                  const float* __restrict__ b1) {
    __shared__ float xs[128 * XS_PITCH];  // 67.6 KB
    __shared__ float ws[FIN * HID];       // 32 KB
    const int tid  = threadIdx.x;
    const int row0 = blockIdx.x * 128;

    // load W1 (2048 float4)
    {
        const float4* wsrc = (const float4*)W1;
        float4* wdst = (float4*)ws;
        #pragma unroll
        for (int i = 0; i < 16; i++) wdst[tid + i * 128] = wsrc[tid + i * 128];
    }
    // load x tile (4096 float4) into pitched smem
    {
        #pragma unroll
        for (int i = 0; i < 32; i++) {
            int f = tid + i * 128;            // [0, 4096)
            int r = f >> 5;
            int o = (f & 31) << 2;
            float4 v = make_float4(0.f, 0.f, 0.f, 0.f);
            if (row0 + r < NNODES) v = *(const float4*)(x + (size_t)(row0 + r) * FIN + o);
            *(float4*)(xs + r * XS_PITCH + o) = v;
        }
    }
    __syncthreads();

    const int rp = tid >> 3;              // 0..15 -> rows rp*8..rp*8+7
    const int cg = tid & 7;               // 8-col group
    const float* wcol = ws + cg * 8;
    const float* xr = xs + (rp * 8) * XS_PITCH;

    u64 acc[8][4];
    #pragma unroll
    for (int r = 0; r < 8; r++)
        #pragma unroll
        for (int j = 0; j < 4; j++) acc[r][j] = 0ull;

    #pragma unroll 2
    for (int k = 0; k < FIN; k += 4) {
        float4 xa[8];
        #pragma unroll
        for (int r = 0; r < 8; r++)
            xa[r] = *(const float4*)(xr + r * XS_PITCH + k);
        #pragma unroll
        for (int kk = 0; kk < 4; kk++) {
            W4 w0, w1;
            w0.v = *(const float4*)(wcol + (k + kk) * HID);
            w1.v = *(const float4*)(wcol + (k + kk) * HID + 4);
            #pragma unroll
            for (int r = 0; r < 8; r++) {
                u64 xv = pack2((&xa[r].x)[kk]);
                acc[r][0] = ffma2(w0.u.lo, xv, acc[r][0]);
                acc[r][1] = ffma2(w0.u.hi, xv, acc[r][1]);
                acc[r][2] = ffma2(w1.u.lo, xv, acc[r][2]);
                acc[r][3] = ffma2(w1.u.hi, xv, acc[r][3]);
            }
        }
    }

    float4 bb0 = *(const float4*)(b1 + cg * 8);
    float4 bb1 = *(const float4*)(b1 + cg * 8 + 4);
    #pragma unroll
    for (int r = 0; r < 8; r++) {
        int row = row0 + rp * 8 + r;
        if (row >= NNODES) continue;
        float di = g_dinv[row];
        F2 a0, a1, a2, a3;
        a0.u = acc[r][0]; a1.u = acc[r][1]; a2.u = acc[r][2]; a3.u = acc[r][3];
        // pre-scaled h1: h1s = h1 * dinv[row]
        float4 o0 = make_float4(a0.f.x * di, a0.f.y * di, a1.f.x * di, a1.f.y * di);
        float4 o1 = make_float4(a2.f.x * di, a2.f.y * di, a3.f.x * di, a3.f.y * di);
        float* hp = g_h1 + (size_t)row * HID + cg * 8;
        *(float4*)(hp)     = o0;
        *(float4*)(hp + 4) = o1;
        // agg1 init: self-loop = h1s * dinv + b1
        float4 g0 = make_float4(fmaf(o0.x, di, bb0.x), fmaf(o0.y, di, bb0.y),
                                fmaf(o0.z, di, bb0.z), fmaf(o0.w, di, bb0.w));
        float4 g1 = make_float4(fmaf(o1.x, di, bb1.x), fmaf(o1.y, di, bb1.y),
                                fmaf(o1.z, di, bb1.z), fmaf(o1.w, di, bb1.w));
        float* ap = g_agg1 + (size_t)row * HID + cg * 8;
        *(float4*)(ap)     = g0;
        *(float4*)(ap + 4) = g1;
    }
}

// ---------------- scatter layer 1: agg1[dst] += h1s[src]*dinv[dst] ----------------
// 16 lanes per edge (lane j owns float4 chunk j) — coalesced gather + reduce.
__global__ void k_scatter1(const int* __restrict__ src, const int* __restrict__ dst) {
    long long t = (long long)blockIdx.x * blockDim.x + threadIdx.x;
    if (t >= (long long)NEDGES * 16) return;
    int e = (int)(t >> 4);
    int g = (int)(t & 15);
    int s = src[e], d = dst[e];
    float norm = g_dinv[d];                       // h1s already has dinv[src]
    float4 v = *(const float4*)(g_h1 + (size_t)s * HID + g * 4);
    red_add_v4(g_agg1 + (size_t)d * HID + g * 4,
               v.x * norm, v.y * norm, v.z * norm, v.w * norm);
}

// ---------------- GEMM2: h2s = (relu(agg1) @ W2)*dinv ; out = h2s*dinv + b2 ----------------
#define XS2_PITCH 68
__global__ void __launch_bounds__(256) k_gemm2(const float* __restrict__ W2,
                                               const float* __restrict__ b2,
                                               float* __restrict__ out) {
    __shared__ float xs[64 * XS2_PITCH];
    __shared__ float ws[HID * 64];
    const int tid  = threadIdx.x;
    const int row0 = blockIdx.x * 64;

    #pragma unroll
    for (int i = 0; i < 16; i++) {
        int idx = tid + i * 256;
        int k = idx >> 6, c = idx & 63;
        ws[idx] = (c < NCLS) ? W2[k * NCLS + c] : 0.0f;
    }
    #pragma unroll
    for (int i = 0; i < 4; i++) {
        int f = tid + i * 256;
        int r = f >> 4;
        int o = (f & 15) << 2;
        float4 v = make_float4(0.f, 0.f, 0.f, 0.f);
        if (row0 + r < NNODES) {
            float4 a = *(const float4*)(g_agg1 + (size_t)(row0 + r) * HID + o);
            v = make_float4(fmaxf(a.x, 0.f), fmaxf(a.y, 0.f),
                            fmaxf(a.z, 0.f), fmaxf(a.w, 0.f));
        }
        *(float4*)(xs + r * XS2_PITCH + o) = v;
    }
    __syncthreads();

    const int rp = tid >> 3;
    const int cg = tid & 7;
    if (cg >= 5) return;                  // cols 40..63 are padding
    const int r0 = rp * 2;
    const float* xr0 = xs + r0 * XS2_PITCH;
    const float* xr1 = xs + (r0 + 1) * XS2_PITCH;
    const float* wcol = ws + cg * 8;

    u64 acc[2][4];
    #pragma unroll
    for (int r = 0; r < 2; r++)
        #pragma unroll
        for (int j = 0; j < 4; j++) acc[r][j] = 0ull;

    #pragma unroll 4
    for (int k = 0; k < HID; k += 4) {
        float4 xa = *(const float4*)(xr0 + k);
        float4 xb = *(const float4*)(xr1 + k);
        #pragma unroll
        for (int kk = 0; kk < 4; kk++) {
            u64 xa2 = pack2((&xa.x)[kk]);
            u64 xb2 = pack2((&xb.x)[kk]);
            W4 w0, w1;
            w0.v = *(const float4*)(wcol + (k + kk) * 64);
            w1.v = *(const float4*)(wcol + (k + kk) * 64 + 4);
            acc[0][0] = ffma2(w0.u.lo, xa2, acc[0][0]);
            acc[0][1] = ffma2(w0.u.hi, xa2, acc[0][1]);
            acc[0][2] = ffma2(w1.u.lo, xa2, acc[0][2]);
            acc[0][3] = ffma2(w1.u.hi, xa2, acc[0][3]);
            acc[1][0] = ffma2(w0.u.lo, xb2, acc[1][0]);
            acc[1][1] = ffma2(w0.u.hi, xb2, acc[1][1]);
            acc[1][2] = ffma2(w1.u.lo, xb2, acc[1][2]);
            acc[1][3] = ffma2(w1.u.hi, xb2, acc[1][3]);
        }
    }

    float4 bb0 = *(const float4*)(b2 + cg * 8);
    float4 bb1 = *(const float4*)(b2 + cg * 8 + 4);
    #pragma unroll
    for (int r = 0; r < 2; r++) {
        int row = row0 + r0 + r;
        if (row >= NNODES) continue;
        float di = g_dinv[row];
        F2 a0, a1, a2, a3;
        a0.u = acc[r][0]; a1.u = acc[r][1]; a2.u = acc[r][2]; a3.u = acc[r][3];
        // pre-scaled h2: h2s = h2 * dinv[row]
        float4 o0 = make_float4(a0.f.x * di, a0.f.y * di, a1.f.x * di, a1.f.y * di);
        float4 o1 = make_float4(a2.f.x * di, a2.f.y * di, a3.f.x * di, a3.f.y * di);
        float* hp = g_h2 + (size_t)row * NCLS + cg * 8;
        *(float4*)(hp)     = o0;
        *(float4*)(hp + 4) = o1;
        // out init: self-loop = h2s * dinv + b2
        float4 g0 = make_float4(fmaf(o0.x, di, bb0.x), fmaf(o0.y, di, bb0.y),
                                fmaf(o0.z, di, bb0.z), fmaf(o0.w, di, bb0.w));
        float4 g1 = make_float4(fmaf(o1.x, di, bb1.x), fmaf(o1.y, di, bb1.y),
                                fmaf(o1.z, di, bb1.z), fmaf(o1.w, di, bb1.w));
        float* op = out + (size_t)row * NCLS + cg * 8;
        *(float4*)(op)     = g0;
        *(float4*)(op + 4) = g1;
    }
}

// ---------------- scatter layer 2: out[dst] += h2s[src]*dinv[dst] ----------------
// 10 float4 groups per edge.
__global__ void k_scatter2(const int* __restrict__ src, const int* __restrict__ dst,
                           float* __restrict__ out) {
    long long t = (long long)blockIdx.x * blockDim.x + threadIdx.x;
    if (t >= (long long)NEDGES * 10) return;
    int e = (int)(t / 10);
    int g = (int)(t - (long long)e * 10);
    int s = src[e], d = dst[e];
    float norm = g_dinv[d];                       // h2s already has dinv[src]
    float4 v = *(const float4*)(g_h2 + (size_t)s * NCLS + g * 4);
    red_add_v4(out + (size_t)d * NCLS + g * 4,
               v.x * norm, v.y * norm, v.z * norm, v.w * norm);
}

// ---------------- launch ----------------
extern "C" void kernel_launch(void* const* d_in, const int* in_sizes, int n_in,
                              void* d_out, int out_size) {
    const float* x   = (const float*)d_in[0];
    const int*   ei  = (const int*)d_in[1];
    const float* W1  = (const float*)d_in[2];
    const float* b1  = (const float*)d_in[3];
    const float* W2  = (const float*)d_in[4];
    const float* b2  = (const float*)d_in[5];
    float* out = (float*)d_out;

    const int* src = ei;
    const int* dst = ei + NEDGES;

    k_init_deg<<<(NNODES + 255) / 256, 256>>>();
    k_count_deg<<<(NEDGES + 255) / 256, 256>>>(dst);
    k_dinv<<<(NNODES + 255) / 256, 256>>>();

    k_gemm1<<<(NNODES + 127) / 128, 128>>>(x, W1, b1);
    {
        long long tot = (long long)NEDGES * 16;
        k_scatter1<<<(unsigned)((tot + 255) / 256), 256>>>(src, dst);
    }
    k_gemm2<<<(NNODES + 63) / 64, 256>>>(W2, b2, out);
    {
        long long tot = (long long)NEDGES * 10;
        k_scatter2<<<(unsigned)((tot + 255) / 256), 256>>>(src, dst, out);
    }
}

// round 7
// speedup vs baseline: 2.1254x; 1.3706x over previous
#include <cuda_runtime.h>
#include <cstdint>

#define NNODES 100000
#define NEDGES 1600000
#define FIN    128
#define HID    64
#define NCLS   40

#define SCAN_BLOCKS 98   // 98 * 1024 >= NNODES

// ---------------- device scratch (allocation-free) ----------------
__device__ int   g_hist[NNODES];
__device__ int   g_cnt[NNODES];
__device__ int   g_offs[NNODES + 1];
__device__ int   g_bsum[SCAN_BLOCKS];
__device__ int   g_boff[SCAN_BLOCKS];
__device__ int   g_csr_src[NEDGES];
__device__ float g_dinv[NNODES];
__device__ float g_h1[(size_t)NNODES * HID];     // (x @ W1) * dinv[row]
__device__ float g_agg1[(size_t)NNODES * HID];
__device__ float g_h2[(size_t)NNODES * NCLS];    // (relu(agg1) @ W2) * dinv[row]

// ---------------- helpers ----------------
typedef unsigned long long u64;
__device__ __forceinline__ u64 ffma2(u64 a, u64 b, u64 c) {
    u64 d;
    asm("fma.rn.f32x2 %0, %1, %2, %3;" : "=l"(d) : "l"(a), "l"(b), "l"(c));
    return d;
}
__device__ __forceinline__ u64 pack2(float x) {
    u64 d;
    asm("mov.b64 %0, {%1, %1};" : "=l"(d) : "f"(x));
    return d;
}
union F2 { u64 u; float2 f; };
union W4 { float4 v; struct { u64 lo, hi; } u; };

// ---------------- CSR build ----------------
__global__ void k_zero() {
    int i = blockIdx.x * blockDim.x + threadIdx.x;
    if (i < NNODES) { g_hist[i] = 0; g_cnt[i] = 0; }
}
__global__ void k_hist(const int* __restrict__ dst) {
    int e = blockIdx.x * blockDim.x + threadIdx.x;
    if (e < NEDGES) atomicAdd(&g_hist[dst[e]], 1);
}
// block-level inclusive scan -> local exclusive offsets + block sums + dinv
__global__ void __launch_bounds__(1024) k_scan1() {
    __shared__ int sh[1024];
    int i = blockIdx.x * 1024 + threadIdx.x;
    int h = (i < NNODES) ? g_hist[i] : 0;
    sh[threadIdx.x] = h;
    __syncthreads();
    #pragma unroll
    for (int ofs = 1; ofs < 1024; ofs <<= 1) {
        int v = (threadIdx.x >= ofs) ? sh[threadIdx.x - ofs] : 0;
        __syncthreads();
        sh[threadIdx.x] += v;
        __syncthreads();
    }
    if (i < NNODES) {
        g_offs[i] = sh[threadIdx.x] - h;              // local exclusive
        g_dinv[i] = rsqrtf((float)(h + 1));           // deg incl self-loop
    }
    if (threadIdx.x == 1023) g_bsum[blockIdx.x] = sh[1023];
}
__global__ void k_scan2() {
    if (threadIdx.x == 0) {
        int run = 0;
        #pragma unroll
        for (int b = 0; b < SCAN_BLOCKS; b++) {
            int v = g_bsum[b];
            g_boff[b] = run;
            run += v;
        }
    }
}
__global__ void k_scan3() {
    int i = blockIdx.x * blockDim.x + threadIdx.x;
    if (i < NNODES) g_offs[i] += g_boff[i >> 10];
    if (i == 0) g_offs[NNODES] = NEDGES;
}
__global__ void k_fill(const int* __restrict__ src, const int* __restrict__ dst) {
    int e = blockIdx.x * blockDim.x + threadIdx.x;
    if (e >= NEDGES) return;
    int s = src[e], d = dst[e];
    int pos = g_offs[d] + atomicAdd(&g_cnt[d], 1);
    g_csr_src[pos] = s;
}

// ---------------- GEMM1: h1s = (x @ W1) * dinv ----------------
// 128 threads, 128-row tile, thread = 8 rows x 8 cols via f32x2 FMA.
#define XS_PITCH 132
__global__ void __launch_bounds__(128, 2) k_gemm1(const float* __restrict__ x,
                                                  const float* __restrict__ W1) {
    __shared__ float xs[128 * XS_PITCH];  // 67.6 KB
    __shared__ float ws[FIN * HID];       // 32 KB
    const int tid  = threadIdx.x;
    const int row0 = blockIdx.x * 128;

    {
        const float4* wsrc = (const float4*)W1;
        float4* wdst = (float4*)ws;
        #pragma unroll
        for (int i = 0; i < 16; i++) wdst[tid + i * 128] = wsrc[tid + i * 128];
    }
    {
        #pragma unroll
        for (int i = 0; i < 32; i++) {
            int f = tid + i * 128;            // [0, 4096)
            int r = f >> 5;
            int o = (f & 31) << 2;
            float4 v = make_float4(0.f, 0.f, 0.f, 0.f);
            if (row0 + r < NNODES) v = *(const float4*)(x + (size_t)(row0 + r) * FIN + o);
            *(float4*)(xs + r * XS_PITCH + o) = v;
        }
    }
    __syncthreads();

    const int rp = tid >> 3;
    const int cg = tid & 7;
    const float* wcol = ws + cg * 8;
    const float* xr = xs + (rp * 8) * XS_PITCH;

    u64 acc[8][4];
    #pragma unroll
    for (int r = 0; r < 8; r++)
        #pragma unroll
        for (int j = 0; j < 4; j++) acc[r][j] = 0ull;

    #pragma unroll 2
    for (int k = 0; k < FIN; k += 4) {
        float4 xa[8];
        #pragma unroll
        for (int r = 0; r < 8; r++)
            xa[r] = *(const float4*)(xr + r * XS_PITCH + k);
        #pragma unroll
        for (int kk = 0; kk < 4; kk++) {
            W4 w0, w1;
            w0.v = *(const float4*)(wcol + (k + kk) * HID);
            w1.v = *(const float4*)(wcol + (k + kk) * HID + 4);
            #pragma unroll
            for (int r = 0; r < 8; r++) {
                u64 xv = pack2((&xa[r].x)[kk]);
                acc[r][0] = ffma2(w0.u.lo, xv, acc[r][0]);
                acc[r][1] = ffma2(w0.u.hi, xv, acc[r][1]);
                acc[r][2] = ffma2(w1.u.lo, xv, acc[r][2]);
                acc[r][3] = ffma2(w1.u.hi, xv, acc[r][3]);
            }
        }
    }

    #pragma unroll
    for (int r = 0; r < 8; r++) {
        int row = row0 + rp * 8 + r;
        if (row >= NNODES) continue;
        float di = g_dinv[row];
        F2 a0, a1, a2, a3;
        a0.u = acc[r][0]; a1.u = acc[r][1]; a2.u = acc[r][2]; a3.u = acc[r][3];
        float* hp = g_h1 + (size_t)row * HID + cg * 8;
        *(float4*)(hp)     = make_float4(a0.f.x * di, a0.f.y * di, a1.f.x * di, a1.f.y * di);
        *(float4*)(hp + 4) = make_float4(a2.f.x * di, a2.f.y * di, a3.f.x * di, a3.f.y * di);
    }
}

// ---------------- agg1: gather; agg1[n] = (h1s[n] + sum h1s[src]) * dinv[n] + b1 ----------------
// 16 lanes per node, lane j owns float4 chunk j; MLP-4 unrolled edge walk.
__global__ void __launch_bounds__(256) k_agg1(const float* __restrict__ b1) {
    int t = blockIdx.x * 256 + threadIdx.x;
    int n = t >> 4;
    if (n >= NNODES) return;
    int j = t & 15;

    int p0 = g_offs[n], p1 = g_offs[n + 1];
    // self-loop term seeds the accumulator
    float4 acc = *(const float4*)(g_h1 + (size_t)n * HID + j * 4);
    int p = p0;
    for (; p + 4 <= p1; p += 4) {
        int s0 = g_csr_src[p],     s1 = g_csr_src[p + 1];
        int s2 = g_csr_src[p + 2], s3 = g_csr_src[p + 3];
        float4 v0 = *(const float4*)(g_h1 + (size_t)s0 * HID + j * 4);
        float4 v1 = *(const float4*)(g_h1 + (size_t)s1 * HID + j * 4);
        float4 v2 = *(const float4*)(g_h1 + (size_t)s2 * HID + j * 4);
        float4 v3 = *(const float4*)(g_h1 + (size_t)s3 * HID + j * 4);
        acc.x += (v0.x + v1.x) + (v2.x + v3.x);
        acc.y += (v0.y + v1.y) + (v2.y + v3.y);
        acc.z += (v0.z + v1.z) + (v2.z + v3.z);
        acc.w += (v0.w + v1.w) + (v2.w + v3.w);
    }
    for (; p < p1; p++) {
        int s = g_csr_src[p];
        float4 v = *(const float4*)(g_h1 + (size_t)s * HID + j * 4);
        acc.x += v.x; acc.y += v.y; acc.z += v.z; acc.w += v.w;
    }
    float di = g_dinv[n];
    float4 bb = *(const float4*)(b1 + j * 4);
    float4 o = make_float4(fmaf(acc.x, di, bb.x), fmaf(acc.y, di, bb.y),
                           fmaf(acc.z, di, bb.z), fmaf(acc.w, di, bb.w));
    *(float4*)(g_agg1 + (size_t)n * HID + j * 4) = o;
}

// ---------------- GEMM2: h2s = (relu(agg1) @ W2) * dinv ----------------
#define XS2_PITCH 68
__global__ void __launch_bounds__(256) k_gemm2(const float* __restrict__ W2) {
    __shared__ float xs[64 * XS2_PITCH];
    __shared__ float ws[HID * 64];
    const int tid  = threadIdx.x;
    const int row0 = blockIdx.x * 64;

    #pragma unroll
    for (int i = 0; i < 16; i++) {
        int idx = tid + i * 256;
        int k = idx >> 6, c = idx & 63;
        ws[idx] = (c < NCLS) ? W2[k * NCLS + c] : 0.0f;
    }
    #pragma unroll
    for (int i = 0; i < 4; i++) {
        int f = tid + i * 256;
        int r = f >> 4;
        int o = (f & 15) << 2;
        float4 v = make_float4(0.f, 0.f, 0.f, 0.f);
        if (row0 + r < NNODES) {
            float4 a = *(const float4*)(g_agg1 + (size_t)(row0 + r) * HID + o);
            v = make_float4(fmaxf(a.x, 0.f), fmaxf(a.y, 0.f),
                            fmaxf(a.z, 0.f), fmaxf(a.w, 0.f));
        }
        *(float4*)(xs + r * XS2_PITCH + o) = v;
    }
    __syncthreads();

    const int rp = tid >> 3;
    const int cg = tid & 7;
    if (cg >= 5) return;                  // cols 40..63 are padding
    const int r0 = rp * 2;
    const float* xr0 = xs + r0 * XS2_PITCH;
    const float* xr1 = xs + (r0 + 1) * XS2_PITCH;
    const float* wcol = ws + cg * 8;

    u64 acc[2][4];
    #pragma unroll
    for (int r = 0; r < 2; r++)
        #pragma unroll
        for (int j = 0; j < 4; j++) acc[r][j] = 0ull;

    #pragma unroll 4
    for (int k = 0; k < HID; k += 4) {
        float4 xa = *(const float4*)(xr0 + k);
        float4 xb = *(const float4*)(xr1 + k);
        #pragma unroll
        for (int kk = 0; kk < 4; kk++) {
            u64 xa2 = pack2((&xa.x)[kk]);
            u64 xb2 = pack2((&xb.x)[kk]);
            W4 w0, w1;
            w0.v = *(const float4*)(wcol + (k + kk) * 64);
            w1.v = *(const float4*)(wcol + (k + kk) * 64 + 4);
            acc[0][0] = ffma2(w0.u.lo, xa2, acc[0][0]);
            acc[0][1] = ffma2(w0.u.hi, xa2, acc[0][1]);
            acc[0][2] = ffma2(w1.u.lo, xa2, acc[0][2]);
            acc[0][3] = ffma2(w1.u.hi, xa2, acc[0][3]);
            acc[1][0] = ffma2(w0.u.lo, xb2, acc[1][0]);
            acc[1][1] = ffma2(w0.u.hi, xb2, acc[1][1]);
            acc[1][2] = ffma2(w1.u.lo, xb2, acc[1][2]);
            acc[1][3] = ffma2(w1.u.hi, xb2, acc[1][3]);
        }
    }

    #pragma unroll
    for (int r = 0; r < 2; r++) {
        int row = row0 + r0 + r;
        if (row >= NNODES) continue;
        float di = g_dinv[row];
        F2 a0, a1, a2, a3;
        a0.u = acc[r][0]; a1.u = acc[r][1]; a2.u = acc[r][2]; a3.u = acc[r][3];
        float* hp = g_h2 + (size_t)row * NCLS + cg * 8;
        *(float4*)(hp)     = make_float4(a0.f.x * di, a0.f.y * di, a1.f.x * di, a1.f.y * di);
        *(float4*)(hp + 4) = make_float4(a2.f.x * di, a2.f.y * di, a3.f.x * di, a3.f.y * di);
    }
}

// ---------------- agg2: gather; out[n] = (h2s[n] + sum h2s[src]) * dinv[n] + b2 ----------------
// 10 lanes per node (lane j owns float4 chunk j of NCLS=40).
__global__ void __launch_bounds__(256) k_agg2(const float* __restrict__ b2,
                                              float* __restrict__ out) {
    int t = blockIdx.x * 256 + threadIdx.x;
    int n = t / 10;
    if (n >= NNODES) return;
    int j = t - n * 10;

    int p0 = g_offs[n], p1 = g_offs[n + 1];
    float4 acc = *(const float4*)(g_h2 + (size_t)n * NCLS + j * 4);
    int p = p0;
    for (; p + 4 <= p1; p += 4) {
        int s0 = g_csr_src[p],     s1 = g_csr_src[p + 1];
        int s2 = g_csr_src[p + 2], s3 = g_csr_src[p + 3];
        float4 v0 = *(const float4*)(g_h2 + (size_t)s0 * NCLS + j * 4);
        float4 v1 = *(const float4*)(g_h2 + (size_t)s1 * NCLS + j * 4);
        float4 v2 = *(const float4*)(g_h2 + (size_t)s2 * NCLS + j * 4);
        float4 v3 = *(const float4*)(g_h2 + (size_t)s3 * NCLS + j * 4);
        acc.x += (v0.x + v1.x) + (v2.x + v3.x);
        acc.y += (v0.y + v1.y) + (v2.y + v3.y);
        acc.z += (v0.z + v1.z) + (v2.z + v3.z);
        acc.w += (v0.w + v1.w) + (v2.w + v3.w);
    }
    for (; p < p1; p++) {
        int s = g_csr_src[p];
        float4 v = *(const float4*)(g_h2 + (size_t)s * NCLS + j * 4);
        acc.x += v.x; acc.y += v.y; acc.z += v.z; acc.w += v.w;
    }
    float di = g_dinv[n];
    float4 bb = *(const float4*)(b2 + j * 4);
    float4 o = make_float4(fmaf(acc.x, di, bb.x), fmaf(acc.y, di, bb.y),
                           fmaf(acc.z, di, bb.z), fmaf(acc.w, di, bb.w));
    *(float4*)(out + (size_t)n * NCLS + j * 4) = o;
}

// ---------------- launch ----------------
extern "C" void kernel_launch(void* const* d_in, const int* in_sizes, int n_in,
                              void* d_out, int out_size) {
    const float* x   = (const float*)d_in[0];
    const int*   ei  = (const int*)d_in[1];
    const float* W1  = (const float*)d_in[2];
    const float* b1  = (const float*)d_in[3];
    const float* W2  = (const float*)d_in[4];
    const float* b2  = (const float*)d_in[5];
    float* out = (float*)d_out;

    const int* src = ei;
    const int* dst = ei + NEDGES;

    // CSR build + dinv
    k_zero<<<(NNODES + 255) / 256, 256>>>();
    k_hist<<<(NEDGES + 255) / 256, 256>>>(dst);
    k_scan1<<<SCAN_BLOCKS, 1024>>>();
    k_scan2<<<1, 32>>>();
    k_scan3<<<(NNODES + 255) / 256, 256>>>();
    k_fill<<<(NEDGES + 255) / 256, 256>>>(src, dst);

    // layer 1
    k_gemm1<<<(NNODES + 127) / 128, 128>>>(x, W1);
    k_agg1<<<(NNODES * 16 + 255) / 256, 256>>>(b1);

    // layer 2
    k_gemm2<<<(NNODES + 63) / 64, 256>>>(W2);
    k_agg2<<<(NNODES * 10 + 255) / 256, 256>>>(b2, out);
}

// round 8
// speedup vs baseline: 2.1857x; 1.0284x over previous
#include <cuda_runtime.h>
#include <cstdint>

#define NNODES 100000
#define NEDGES 1600000
#define FIN    128
#define HID    64
#define NCLS   40

#define SCAN_BLOCKS 98   // 98 * 1024 >= NNODES

// ---------------- device scratch (allocation-free) ----------------
__device__ int   g_hist[NNODES];
__device__ int   g_cnt[NNODES];
__device__ int   g_offs[NNODES];          // block-local exclusive offsets
__device__ int   g_bsum[SCAN_BLOCKS];
__device__ int   g_boff[SCAN_BLOCKS];     // global block offsets (exclusive)
__device__ int   g_csr_src[NEDGES];
__device__ float g_dinv[NNODES];
__device__ float g_h1[(size_t)NNODES * HID];     // (x @ W1) * dinv[row]
__device__ float g_agg1[(size_t)NNODES * HID];
__device__ float g_h2[(size_t)NNODES * NCLS];    // (relu(agg1) @ W2) * dinv[row]

// ---------------- helpers ----------------
typedef unsigned long long u64;
__device__ __forceinline__ u64 ffma2(u64 a, u64 b, u64 c) {
    u64 d;
    asm("fma.rn.f32x2 %0, %1, %2, %3;" : "=l"(d) : "l"(a), "l"(b), "l"(c));
    return d;
}
__device__ __forceinline__ u64 pack2(float x) {
    u64 d;
    asm("mov.b64 %0, {%1, %1};" : "=l"(d) : "f"(x));
    return d;
}
union F2 { u64 u; float2 f; };
union W4 { float4 v; struct { u64 lo, hi; } u; };

// global CSR range for node n (offsets are block-local + boff)
__device__ __forceinline__ void node_range(int n, int& p0, int& p1) {
    p0 = g_offs[n] + g_boff[n >> 10];
    int m = n + 1;
    p1 = (m == NNODES) ? NEDGES : (g_offs[m] + g_boff[m >> 10]);
}

// ---------------- CSR build ----------------
__global__ void k_zero() {
    int i = blockIdx.x * blockDim.x + threadIdx.x;
    if (i < NNODES) g_hist[i] = 0;
}
__global__ void k_hist(const int* __restrict__ dst) {
    int e = blockIdx.x * blockDim.x + threadIdx.x;
    if (e < NEDGES) atomicAdd(&g_hist[dst[e]], 1);
}
// block-level scan -> local exclusive offsets + block sums + dinv + cnt=0
__global__ void __launch_bounds__(1024) k_scan1() {
    __shared__ int sh[1024];
    int i = blockIdx.x * 1024 + threadIdx.x;
    int h = (i < NNODES) ? g_hist[i] : 0;
    sh[threadIdx.x] = h;
    __syncthreads();
    #pragma unroll
    for (int ofs = 1; ofs < 1024; ofs <<= 1) {
        int v = (threadIdx.x >= ofs) ? sh[threadIdx.x - ofs] : 0;
        __syncthreads();
        sh[threadIdx.x] += v;
        __syncthreads();
    }
    if (i < NNODES) {
        g_offs[i] = sh[threadIdx.x] - h;              // local exclusive
        g_dinv[i] = rsqrtf((float)(h + 1));           // deg incl self-loop
        g_cnt[i]  = 0;
    }
    if (threadIdx.x == 1023) g_bsum[blockIdx.x] = sh[1023];
}
// parallel 98-element exclusive scan of block sums
__global__ void __launch_bounds__(128) k_scan2() {
    __shared__ int sh[128];
    int t = threadIdx.x;
    int v = (t < SCAN_BLOCKS) ? g_bsum[t] : 0;
    sh[t] = v;
    __syncthreads();
    #pragma unroll
    for (int ofs = 1; ofs < 128; ofs <<= 1) {
        int u = (t >= ofs) ? sh[t - ofs] : 0;
        __syncthreads();
        sh[t] += u;
        __syncthreads();
    }
    if (t < SCAN_BLOCKS) g_boff[t] = sh[t] - v;       // exclusive
}
__global__ void k_fill(const int* __restrict__ src, const int* __restrict__ dst) {
    int e = blockIdx.x * blockDim.x + threadIdx.x;
    if (e >= NEDGES) return;
    int s = src[e], d = dst[e];
    int pos = g_offs[d] + g_boff[d >> 10] + atomicAdd(&g_cnt[d], 1);
    g_csr_src[pos] = s;
}

// ---------------- GEMM1: h1s = (x @ W1) * dinv ----------------
#define XS_PITCH 132
__global__ void __launch_bounds__(128, 2) k_gemm1(const float* __restrict__ x,
                                                  const float* __restrict__ W1) {
    __shared__ float xs[128 * XS_PITCH];  // 67.6 KB
    __shared__ float ws[FIN * HID];       // 32 KB
    const int tid  = threadIdx.x;
    const int row0 = blockIdx.x * 128;

    {
        const float4* wsrc = (const float4*)W1;
        float4* wdst = (float4*)ws;
        #pragma unroll
        for (int i = 0; i < 16; i++) wdst[tid + i * 128] = wsrc[tid + i * 128];
    }
    {
        #pragma unroll
        for (int i = 0; i < 32; i++) {
            int f = tid + i * 128;
            int r = f >> 5;
            int o = (f & 31) << 2;
            float4 v = make_float4(0.f, 0.f, 0.f, 0.f);
            if (row0 + r < NNODES) v = *(const float4*)(x + (size_t)(row0 + r) * FIN + o);
            *(float4*)(xs + r * XS_PITCH + o) = v;
        }
    }
    __syncthreads();

    const int rp = tid >> 3;
    const int cg = tid & 7;
    const float* wcol = ws + cg * 8;
    const float* xr = xs + (rp * 8) * XS_PITCH;

    u64 acc[8][4];
    #pragma unroll
    for (int r = 0; r < 8; r++)
        #pragma unroll
        for (int j = 0; j < 4; j++) acc[r][j] = 0ull;

    #pragma unroll 2
    for (int k = 0; k < FIN; k += 4) {
        float4 xa[8];
        #pragma unroll
        for (int r = 0; r < 8; r++)
            xa[r] = *(const float4*)(xr + r * XS_PITCH + k);
        #pragma unroll
        for (int kk = 0; kk < 4; kk++) {
            W4 w0, w1;
            w0.v = *(const float4*)(wcol + (k + kk) * HID);
            w1.v = *(const float4*)(wcol + (k + kk) * HID + 4);
            #pragma unroll
            for (int r = 0; r < 8; r++) {
                u64 xv = pack2((&xa[r].x)[kk]);
                acc[r][0] = ffma2(w0.u.lo, xv, acc[r][0]);
                acc[r][1] = ffma2(w0.u.hi, xv, acc[r][1]);
                acc[r][2] = ffma2(w1.u.lo, xv, acc[r][2]);
                acc[r][3] = ffma2(w1.u.hi, xv, acc[r][3]);
            }
        }
    }

    #pragma unroll
    for (int r = 0; r < 8; r++) {
        int row = row0 + rp * 8 + r;
        if (row >= NNODES) continue;
        float di = g_dinv[row];
        F2 a0, a1, a2, a3;
        a0.u = acc[r][0]; a1.u = acc[r][1]; a2.u = acc[r][2]; a3.u = acc[r][3];
        float* hp = g_h1 + (size_t)row * HID + cg * 8;
        *(float4*)(hp)     = make_float4(a0.f.x * di, a0.f.y * di, a1.f.x * di, a1.f.y * di);
        *(float4*)(hp + 4) = make_float4(a2.f.x * di, a2.f.y * di, a3.f.x * di, a3.f.y * di);
    }
}

// ---------------- agg1: agg1[n] = (h1s[n] + sum h1s[src]) * dinv[n] + b1 ----------------
// 16 lanes per node, lane j owns float4 chunk j; MLP-8 unrolled edge walk.
__global__ void __launch_bounds__(256) k_agg1(const float* __restrict__ b1) {
    int t = blockIdx.x * 256 + threadIdx.x;
    int n = t >> 4;
    if (n >= NNODES) return;
    int j = t & 15;

    int p0, p1;
    node_range(n, p0, p1);
    float4 acc = *(const float4*)(g_h1 + (size_t)n * HID + j * 4);   // self-loop seed
    int p = p0;
    for (; p + 8 <= p1; p += 8) {
        int s[8];
        #pragma unroll
        for (int q = 0; q < 8; q++) s[q] = g_csr_src[p + q];
        float4 v[8];
        #pragma unroll
        for (int q = 0; q < 8; q++)
            v[q] = *(const float4*)(g_h1 + (size_t)s[q] * HID + j * 4);
        #pragma unroll
        for (int q = 0; q < 8; q++) {
            acc.x += v[q].x; acc.y += v[q].y; acc.z += v[q].z; acc.w += v[q].w;
        }
    }
    for (; p + 4 <= p1; p += 4) {
        int s0 = g_csr_src[p],     s1 = g_csr_src[p + 1];
        int s2 = g_csr_src[p + 2], s3 = g_csr_src[p + 3];
        float4 v0 = *(const float4*)(g_h1 + (size_t)s0 * HID + j * 4);
        float4 v1 = *(const float4*)(g_h1 + (size_t)s1 * HID + j * 4);
        float4 v2 = *(const float4*)(g_h1 + (size_t)s2 * HID + j * 4);
        float4 v3 = *(const float4*)(g_h1 + (size_t)s3 * HID + j * 4);
        acc.x += (v0.x + v1.x) + (v2.x + v3.x);
        acc.y += (v0.y + v1.y) + (v2.y + v3.y);
        acc.z += (v0.z + v1.z) + (v2.z + v3.z);
        acc.w += (v0.w + v1.w) + (v2.w + v3.w);
    }
    for (; p < p1; p++) {
        int s = g_csr_src[p];
        float4 v = *(const float4*)(g_h1 + (size_t)s * HID + j * 4);
        acc.x += v.x; acc.y += v.y; acc.z += v.z; acc.w += v.w;
    }
    float di = g_dinv[n];
    float4 bb = *(const float4*)(b1 + j * 4);
    float4 o = make_float4(fmaf(acc.x, di, bb.x), fmaf(acc.y, di, bb.y),
                           fmaf(acc.z, di, bb.z), fmaf(acc.w, di, bb.w));
    *(float4*)(g_agg1 + (size_t)n * HID + j * 4) = o;
}

// ---------------- GEMM2: h2s = (relu(agg1) @ W2) * dinv ----------------
#define XS2_PITCH 68
__global__ void __launch_bounds__(256) k_gemm2(const float* __restrict__ W2) {
    __shared__ float xs[64 * XS2_PITCH];
    __shared__ float ws[HID * 64];
    const int tid  = threadIdx.x;
    const int row0 = blockIdx.x * 64;

    #pragma unroll
    for (int i = 0; i < 16; i++) {
        int idx = tid + i * 256;
        int k = idx >> 6, c = idx & 63;
        ws[idx] = (c < NCLS) ? W2[k * NCLS + c] : 0.0f;
    }
    #pragma unroll
    for (int i = 0; i < 4; i++) {
        int f = tid + i * 256;
        int r = f >> 4;
        int o = (f & 15) << 2;
        float4 v = make_float4(0.f, 0.f, 0.f, 0.f);
        if (row0 + r < NNODES) {
            float4 a = *(const float4*)(g_agg1 + (size_t)(row0 + r) * HID + o);
            v = make_float4(fmaxf(a.x, 0.f), fmaxf(a.y, 0.f),
                            fmaxf(a.z, 0.f), fmaxf(a.w, 0.f));
        }
        *(float4*)(xs + r * XS2_PITCH + o) = v;
    }
    __syncthreads();

    const int rp = tid >> 3;
    const int cg = tid & 7;
    if (cg >= 5) return;                  // cols 40..63 are padding
    const int r0 = rp * 2;
    const float* xr0 = xs + r0 * XS2_PITCH;
    const float* xr1 = xs + (r0 + 1) * XS2_PITCH;
    const float* wcol = ws + cg * 8;

    u64 acc[2][4];
    #pragma unroll
    for (int r = 0; r < 2; r++)
        #pragma unroll
        for (int j = 0; j < 4; j++) acc[r][j] = 0ull;

    #pragma unroll 4
    for (int k = 0; k < HID; k += 4) {
        float4 xa = *(const float4*)(xr0 + k);
        float4 xb = *(const float4*)(xr1 + k);
        #pragma unroll
        for (int kk = 0; kk < 4; kk++) {
            u64 xa2 = pack2((&xa.x)[kk]);
            u64 xb2 = pack2((&xb.x)[kk]);
            W4 w0, w1;
            w0.v = *(const float4*)(wcol + (k + kk) * 64);
            w1.v = *(const float4*)(wcol + (k + kk) * 64 + 4);
            acc[0][0] = ffma2(w0.u.lo, xa2, acc[0][0]);
            acc[0][1] = ffma2(w0.u.hi, xa2, acc[0][1]);
            acc[0][2] = ffma2(w1.u.lo, xa2, acc[0][2]);
            acc[0][3] = ffma2(w1.u.hi, xa2, acc[0][3]);
            acc[1][0] = ffma2(w0.u.lo, xb2, acc[1][0]);
            acc[1][1] = ffma2(w0.u.hi, xb2, acc[1][1]);
            acc[1][2] = ffma2(w1.u.lo, xb2, acc[1][2]);
            acc[1][3] = ffma2(w1.u.hi, xb2, acc[1][3]);
        }
    }

    #pragma unroll
    for (int r = 0; r < 2; r++) {
        int row = row0 + r0 + r;
        if (row >= NNODES) continue;
        float di = g_dinv[row];
        F2 a0, a1, a2, a3;
        a0.u = acc[r][0]; a1.u = acc[r][1]; a2.u = acc[r][2]; a3.u = acc[r][3];
        float* hp = g_h2 + (size_t)row * NCLS + cg * 8;
        *(float4*)(hp)     = make_float4(a0.f.x * di, a0.f.y * di, a1.f.x * di, a1.f.y * di);
        *(float4*)(hp + 4) = make_float4(a2.f.x * di, a2.f.y * di, a3.f.x * di, a3.f.y * di);
    }
}

// ---------------- agg2: out[n] = (h2s[n] + sum h2s[src]) * dinv[n] + b2 ----------------
// 10 lanes per node (lane j owns float4 chunk j of NCLS=40); MLP-8 walk.
__global__ void __launch_bounds__(256) k_agg2(const float* __restrict__ b2,
                                              float* __restrict__ out) {
    int t = blockIdx.x * 256 + threadIdx.x;
    int n = t / 10;
    if (n >= NNODES) return;
    int j = t - n * 10;

    int p0, p1;
    node_range(n, p0, p1);
    float4 acc = *(const float4*)(g_h2 + (size_t)n * NCLS + j * 4);
    int p = p0;
    for (; p + 8 <= p1; p += 8) {
        int s[8];
        #pragma unroll
        for (int q = 0; q < 8; q++) s[q] = g_csr_src[p + q];
        float4 v[8];
        #pragma unroll
        for (int q = 0; q < 8; q++)
            v[q] = *(const float4*)(g_h2 + (size_t)s[q] * NCLS + j * 4);
        #pragma unroll
        for (int q = 0; q < 8; q++) {
            acc.x += v[q].x; acc.y += v[q].y; acc.z += v[q].z; acc.w += v[q].w;
        }
    }
    for (; p + 4 <= p1; p += 4) {
        int s0 = g_csr_src[p],     s1 = g_csr_src[p + 1];
        int s2 = g_csr_src[p + 2], s3 = g_csr_src[p + 3];
        float4 v0 = *(const float4*)(g_h2 + (size_t)s0 * NCLS + j * 4);
        float4 v1 = *(const float4*)(g_h2 + (size_t)s1 * NCLS + j * 4);
        float4 v2 = *(const float4*)(g_h2 + (size_t)s2 * NCLS + j * 4);
        float4 v3 = *(const float4*)(g_h2 + (size_t)s3 * NCLS + j * 4);
        acc.x += (v0.x + v1.x) + (v2.x + v3.x);
        acc.y += (v0.y + v1.y) + (v2.y + v3.y);
        acc.z += (v0.z + v1.z) + (v2.z + v3.z);
        acc.w += (v0.w + v1.w) + (v2.w + v3.w);
    }
    for (; p < p1; p++) {
        int s = g_csr_src[p];
        float4 v = *(const float4*)(g_h2 + (size_t)s * NCLS + j * 4);
        acc.x += v.x; acc.y += v.y; acc.z += v.z; acc.w += v.w;
    }
    float di = g_dinv[n];
    float4 bb = *(const float4*)(b2 + j * 4);
    float4 o = make_float4(fmaf(acc.x, di, bb.x), fmaf(acc.y, di, bb.y),
                           fmaf(acc.z, di, bb.z), fmaf(acc.w, di, bb.w));
    *(float4*)(out + (size_t)n * NCLS + j * 4) = o;
}

// ---------------- launch ----------------
extern "C" void kernel_launch(void* const* d_in, const int* in_sizes, int n_in,
                              void* d_out, int out_size) {
    const float* x   = (const float*)d_in[0];
    const int*   ei  = (const int*)d_in[1];
    const float* W1  = (const float*)d_in[2];
    const float* b1  = (const float*)d_in[3];
    const float* W2  = (const float*)d_in[4];
    const float* b2  = (const float*)d_in[5];
    float* out = (float*)d_out;

    const int* src = ei;
    const int* dst = ei + NEDGES;

    // CSR build + dinv
    k_zero<<<(NNODES + 255) / 256, 256>>>();
    k_hist<<<(NEDGES + 255) / 256, 256>>>(dst);
    k_scan1<<<SCAN_BLOCKS, 1024>>>();
    k_scan2<<<1, 128>>>();
    k_fill<<<(NEDGES + 255) / 256, 256>>>(src, dst);

    // layer 1
    k_gemm1<<<(NNODES + 127) / 128, 128>>>(x, W1);
    k_agg1<<<(NNODES * 16 + 255) / 256, 256>>>(b1);

    // layer 2
    k_gemm2<<<(NNODES + 63) / 64, 256>>>(W2);
    k_agg2<<<(NNODES * 10 + 255) / 256, 256>>>(b2, out);
}

// round 9
// speedup vs baseline: 2.3298x; 1.0660x over previous
#include <cuda_runtime.h>
#include <cuda_fp16.h>
#include <cstdint>

#define NNODES 100000
#define NEDGES 1600000
#define FIN    128
#define HID    64
#define NCLS   40

#define SCAN_BLOCKS 98   // 98 * 1024 >= NNODES

// ---------------- device scratch (allocation-free) ----------------
__device__ int    g_hist[NNODES];
__device__ int    g_cnt[NNODES];
__device__ int    g_offs[NNODES];          // block-local exclusive offsets
__device__ int    g_bsum[SCAN_BLOCKS];
__device__ int    g_boff[SCAN_BLOCKS];     // global block offsets (exclusive)
__device__ int    g_csr_src[NEDGES];
__device__ float  g_dinv[NNODES];
__device__ __half g_h1h[(size_t)NNODES * HID];    // (x @ W1) * dinv[row], fp16
__device__ float  g_agg1[(size_t)NNODES * HID];   // fp32
__device__ __half g_h2h[(size_t)NNODES * NCLS];   // (relu(agg1) @ W2) * dinv[row], fp16

// ---------------- helpers ----------------
typedef unsigned long long u64;
__device__ __forceinline__ u64 ffma2(u64 a, u64 b, u64 c) {
    u64 d;
    asm("fma.rn.f32x2 %0, %1, %2, %3;" : "=l"(d) : "l"(a), "l"(b), "l"(c));
    return d;
}
__device__ __forceinline__ u64 pack2(float x) {
    u64 d;
    asm("mov.b64 %0, {%1, %1};" : "=l"(d) : "f"(x));
    return d;
}
union F2 { u64 u; float2 f; };
union W4 { float4 v; struct { u64 lo, hi; } u; };

__device__ __forceinline__ float2 h2tof2(uint32_t h) {
    __half2 hh = *reinterpret_cast<__half2*>(&h);
    return __half22float2(hh);
}

// global CSR range for node n
__device__ __forceinline__ void node_range(int n, int& p0, int& p1) {
    p0 = g_offs[n] + g_boff[n >> 10];
    int m = n + 1;
    p1 = (m == NNODES) ? NEDGES : (g_offs[m] + g_boff[m >> 10]);
}

// ---------------- CSR build ----------------
__global__ void k_zero() {
    int i = blockIdx.x * blockDim.x + threadIdx.x;
    if (i < NNODES) g_hist[i] = 0;
}
__global__ void k_hist(const int* __restrict__ dst) {
    int e = blockIdx.x * blockDim.x + threadIdx.x;
    if (e < NEDGES) atomicAdd(&g_hist[dst[e]], 1);
}
__global__ void __launch_bounds__(1024) k_scan1() {
    __shared__ int sh[1024];
    int i = blockIdx.x * 1024 + threadIdx.x;
    int h = (i < NNODES) ? g_hist[i] : 0;
    sh[threadIdx.x] = h;
    __syncthreads();
    #pragma unroll
    for (int ofs = 1; ofs < 1024; ofs <<= 1) {
        int v = (threadIdx.x >= ofs) ? sh[threadIdx.x - ofs] : 0;
        __syncthreads();
        sh[threadIdx.x] += v;
        __syncthreads();
    }
    if (i < NNODES) {
        g_offs[i] = sh[threadIdx.x] - h;
        g_dinv[i] = rsqrtf((float)(h + 1));
        g_cnt[i]  = 0;
    }
    if (threadIdx.x == 1023) g_bsum[blockIdx.x] = sh[1023];
}
__global__ void __launch_bounds__(128) k_scan2() {
    __shared__ int sh[128];
    int t = threadIdx.x;
    int v = (t < SCAN_BLOCKS) ? g_bsum[t] : 0;
    sh[t] = v;
    __syncthreads();
    #pragma unroll
    for (int ofs = 1; ofs < 128; ofs <<= 1) {
        int u = (t >= ofs) ? sh[t - ofs] : 0;
        __syncthreads();
        sh[t] += u;
        __syncthreads();
    }
    if (t < SCAN_BLOCKS) g_boff[t] = sh[t] - v;
}
__global__ void k_fill(const int* __restrict__ src, const int* __restrict__ dst) {
    int e = blockIdx.x * blockDim.x + threadIdx.x;
    if (e >= NEDGES) return;
    int s = src[e], d = dst[e];
    int pos = g_offs[d] + g_boff[d >> 10] + atomicAdd(&g_cnt[d], 1);
    g_csr_src[pos] = s;
}

// ---------------- GEMM1: h1h = (x @ W1) * dinv  (fp16 out) ----------------
#define XS_PITCH 132
__global__ void __launch_bounds__(128, 2) k_gemm1(const float* __restrict__ x,
                                                  const float* __restrict__ W1) {
    __shared__ float xs[128 * XS_PITCH];  // 67.6 KB
    __shared__ float ws[FIN * HID];       // 32 KB
    const int tid  = threadIdx.x;
    const int row0 = blockIdx.x * 128;

    {
        const float4* wsrc = (const float4*)W1;
        float4* wdst = (float4*)ws;
        #pragma unroll
        for (int i = 0; i < 16; i++) wdst[tid + i * 128] = wsrc[tid + i * 128];
    }
    {
        #pragma unroll
        for (int i = 0; i < 32; i++) {
            int f = tid + i * 128;
            int r = f >> 5;
            int o = (f & 31) << 2;
            float4 v = make_float4(0.f, 0.f, 0.f, 0.f);
            if (row0 + r < NNODES) v = *(const float4*)(x + (size_t)(row0 + r) * FIN + o);
            *(float4*)(xs + r * XS_PITCH + o) = v;
        }
    }
    __syncthreads();

    const int rp = tid >> 3;
    const int cg = tid & 7;
    const float* wcol = ws + cg * 8;
    const float* xr = xs + (rp * 8) * XS_PITCH;

    u64 acc[8][4];
    #pragma unroll
    for (int r = 0; r < 8; r++)
        #pragma unroll
        for (int j = 0; j < 4; j++) acc[r][j] = 0ull;

    #pragma unroll 2
    for (int k = 0; k < FIN; k += 4) {
        float4 xa[8];
        #pragma unroll
        for (int r = 0; r < 8; r++)
            xa[r] = *(const float4*)(xr + r * XS_PITCH + k);
        #pragma unroll
        for (int kk = 0; kk < 4; kk++) {
            W4 w0, w1;
            w0.v = *(const float4*)(wcol + (k + kk) * HID);
            w1.v = *(const float4*)(wcol + (k + kk) * HID + 4);
            #pragma unroll
            for (int r = 0; r < 8; r++) {
                u64 xv = pack2((&xa[r].x)[kk]);
                acc[r][0] = ffma2(w0.u.lo, xv, acc[r][0]);
                acc[r][1] = ffma2(w0.u.hi, xv, acc[r][1]);
                acc[r][2] = ffma2(w1.u.lo, xv, acc[r][2]);
                acc[r][3] = ffma2(w1.u.hi, xv, acc[r][3]);
            }
        }
    }

    #pragma unroll
    for (int r = 0; r < 8; r++) {
        int row = row0 + rp * 8 + r;
        if (row >= NNODES) continue;
        float di = g_dinv[row];
        F2 a0, a1, a2, a3;
        a0.u = acc[r][0]; a1.u = acc[r][1]; a2.u = acc[r][2]; a3.u = acc[r][3];
        uint4 st;
        __half2* sp = (__half2*)&st;
        sp[0] = __floats2half2_rn(a0.f.x * di, a0.f.y * di);
        sp[1] = __floats2half2_rn(a1.f.x * di, a1.f.y * di);
        sp[2] = __floats2half2_rn(a2.f.x * di, a2.f.y * di);
        sp[3] = __floats2half2_rn(a3.f.x * di, a3.f.y * di);
        *(uint4*)(g_h1h + (size_t)row * HID + cg * 8) = st;
    }
}

// ---------------- agg1: agg1[n] = (h1h[n] + sum h1h[src]) * dinv[n] + b1 ----------------
// 8 lanes per node; lane j owns 8 halves (16B) = features j*8..j*8+7.
__global__ void __launch_bounds__(256) k_agg1(const float* __restrict__ b1) {
    int t = blockIdx.x * 256 + threadIdx.x;
    int n = t >> 3;
    if (n >= NNODES) return;
    int j = t & 7;

    int p0, p1;
    node_range(n, p0, p1);

    float acc[8];
    {   // self-loop seed
        uint4 v = *(const uint4*)(g_h1h + (size_t)n * HID + j * 8);
        float2 f0 = h2tof2(v.x), f1 = h2tof2(v.y), f2 = h2tof2(v.z), f3 = h2tof2(v.w);
        acc[0] = f0.x; acc[1] = f0.y; acc[2] = f1.x; acc[3] = f1.y;
        acc[4] = f2.x; acc[5] = f2.y; acc[6] = f3.x; acc[7] = f3.y;
    }
    int p = p0;
    for (; p + 8 <= p1; p += 8) {
        int s[8];
        #pragma unroll
        for (int q = 0; q < 8; q++) s[q] = g_csr_src[p + q];
        uint4 v[8];
        #pragma unroll
        for (int q = 0; q < 8; q++)
            v[q] = *(const uint4*)(g_h1h + (size_t)s[q] * HID + j * 8);
        #pragma unroll
        for (int q = 0; q < 8; q++) {
            float2 f0 = h2tof2(v[q].x), f1 = h2tof2(v[q].y);
            float2 f2 = h2tof2(v[q].z), f3 = h2tof2(v[q].w);
            acc[0] += f0.x; acc[1] += f0.y; acc[2] += f1.x; acc[3] += f1.y;
            acc[4] += f2.x; acc[5] += f2.y; acc[6] += f3.x; acc[7] += f3.y;
        }
    }
    for (; p < p1; p++) {
        int s = g_csr_src[p];
        uint4 v = *(const uint4*)(g_h1h + (size_t)s * HID + j * 8);
        float2 f0 = h2tof2(v.x), f1 = h2tof2(v.y), f2 = h2tof2(v.z), f3 = h2tof2(v.w);
        acc[0] += f0.x; acc[1] += f0.y; acc[2] += f1.x; acc[3] += f1.y;
        acc[4] += f2.x; acc[5] += f2.y; acc[6] += f3.x; acc[7] += f3.y;
    }
    float di = g_dinv[n];
    float4 bb0 = *(const float4*)(b1 + j * 8);
    float4 bb1 = *(const float4*)(b1 + j * 8 + 4);
    float* ap = g_agg1 + (size_t)n * HID + j * 8;
    *(float4*)(ap)     = make_float4(fmaf(acc[0], di, bb0.x), fmaf(acc[1], di, bb0.y),
                                     fmaf(acc[2], di, bb0.z), fmaf(acc[3], di, bb0.w));
    *(float4*)(ap + 4) = make_float4(fmaf(acc[4], di, bb1.x), fmaf(acc[5], di, bb1.y),
                                     fmaf(acc[6], di, bb1.z), fmaf(acc[7], di, bb1.w));
}

// ---------------- GEMM2: h2h = (relu(agg1) @ W2) * dinv  (fp16 out) ----------------
#define XS2_PITCH 68
__global__ void __launch_bounds__(256) k_gemm2(const float* __restrict__ W2) {
    __shared__ float xs[64 * XS2_PITCH];
    __shared__ float ws[HID * 64];
    const int tid  = threadIdx.x;
    const int row0 = blockIdx.x * 64;

    #pragma unroll
    for (int i = 0; i < 16; i++) {
        int idx = tid + i * 256;
        int k = idx >> 6, c = idx & 63;
        ws[idx] = (c < NCLS) ? W2[k * NCLS + c] : 0.0f;
    }
    #pragma unroll
    for (int i = 0; i < 4; i++) {
        int f = tid + i * 256;
        int r = f >> 4;
        int o = (f & 15) << 2;
        float4 v = make_float4(0.f, 0.f, 0.f, 0.f);
        if (row0 + r < NNODES) {
            float4 a = *(const float4*)(g_agg1 + (size_t)(row0 + r) * HID + o);
            v = make_float4(fmaxf(a.x, 0.f), fmaxf(a.y, 0.f),
                            fmaxf(a.z, 0.f), fmaxf(a.w, 0.f));
        }
        *(float4*)(xs + r * XS2_PITCH + o) = v;
    }
    __syncthreads();

    const int rp = tid >> 3;
    const int cg = tid & 7;
    if (cg >= 5) return;                  // cols 40..63 are padding
    const int r0 = rp * 2;
    const float* xr0 = xs + r0 * XS2_PITCH;
    const float* xr1 = xs + (r0 + 1) * XS2_PITCH;
    const float* wcol = ws + cg * 8;

    u64 acc[2][4];
    #pragma unroll
    for (int r = 0; r < 2; r++)
        #pragma unroll
        for (int j = 0; j < 4; j++) acc[r][j] = 0ull;

    #pragma unroll 4
    for (int k = 0; k < HID; k += 4) {
        float4 xa = *(const float4*)(xr0 + k);
        float4 xb = *(const float4*)(xr1 + k);
        #pragma unroll
        for (int kk = 0; kk < 4; kk++) {
            u64 xa2 = pack2((&xa.x)[kk]);
            u64 xb2 = pack2((&xb.x)[kk]);
            W4 w0, w1;
            w0.v = *(const float4*)(wcol + (k + kk) * 64);
            w1.v = *(const float4*)(wcol + (k + kk) * 64 + 4);
            acc[0][0] = ffma2(w0.u.lo, xa2, acc[0][0]);
            acc[0][1] = ffma2(w0.u.hi, xa2, acc[0][1]);
            acc[0][2] = ffma2(w1.u.lo, xa2, acc[0][2]);
            acc[0][3] = ffma2(w1.u.hi, xa2, acc[0][3]);
            acc[1][0] = ffma2(w0.u.lo, xb2, acc[1][0]);
            acc[1][1] = ffma2(w0.u.hi, xb2, acc[1][1]);
            acc[1][2] = ffma2(w1.u.lo, xb2, acc[1][2]);
            acc[1][3] = ffma2(w1.u.hi, xb2, acc[1][3]);
        }
    }

    #pragma unroll
    for (int r = 0; r < 2; r++) {
        int row = row0 + r0 + r;
        if (row >= NNODES) continue;
        float di = g_dinv[row];
        F2 a0, a1, a2, a3;
        a0.u = acc[r][0]; a1.u = acc[r][1]; a2.u = acc[r][2]; a3.u = acc[r][3];
        uint4 st;
        __half2* sp = (__half2*)&st;
        sp[0] = __floats2half2_rn(a0.f.x * di, a0.f.y * di);
        sp[1] = __floats2half2_rn(a1.f.x * di, a1.f.y * di);
        sp[2] = __floats2half2_rn(a2.f.x * di, a2.f.y * di);
        sp[3] = __floats2half2_rn(a3.f.x * di, a3.f.y * di);
        *(uint4*)(g_h2h + (size_t)row * NCLS + cg * 8) = st;
    }
}

// ---------------- agg2: out[n] = (h2h[n] + sum h2h[src]) * dinv[n] + b2 ----------------
// 5 lanes per node; lane j owns 8 halves (16B) = features j*8..j*8+7 of 40.
__global__ void __launch_bounds__(256) k_agg2(const float* __restrict__ b2,
                                              float* __restrict__ out) {
    int t = blockIdx.x * 256 + threadIdx.x;
    int n = t / 5;
    if (n >= NNODES) return;
    int j = t - n * 5;

    int p0, p1;
    node_range(n, p0, p1);

    float acc[8];
    {
        uint4 v = *(const uint4*)(g_h2h + (size_t)n * NCLS + j * 8);
        float2 f0 = h2tof2(v.x), f1 = h2tof2(v.y), f2 = h2tof2(v.z), f3 = h2tof2(v.w);
        acc[0] = f0.x; acc[1] = f0.y; acc[2] = f1.x; acc[3] = f1.y;
        acc[4] = f2.x; acc[5] = f2.y; acc[6] = f3.x; acc[7] = f3.y;
    }
    int p = p0;
    for (; p + 8 <= p1; p += 8) {
        int s[8];
        #pragma unroll
        for (int q = 0; q < 8; q++) s[q] = g_csr_src[p + q];
        uint4 v[8];
        #pragma unroll
        for (int q = 0; q < 8; q++)
            v[q] = *(const uint4*)(g_h2h + (size_t)s[q] * NCLS + j * 8);
        #pragma unroll
        for (int q = 0; q < 8; q++) {
            float2 f0 = h2tof2(v[q].x), f1 = h2tof2(v[q].y);
            float2 f2 = h2tof2(v[q].z), f3 = h2tof2(v[q].w);
            acc[0] += f0.x; acc[1] += f0.y; acc[2] += f1.x; acc[3] += f1.y;
            acc[4] += f2.x; acc[5] += f2.y; acc[6] += f3.x; acc[7] += f3.y;
        }
    }
    for (; p < p1; p++) {
        int s = g_csr_src[p];
        uint4 v = *(const uint4*)(g_h2h + (size_t)s * NCLS + j * 8);
        float2 f0 = h2tof2(v.x), f1 = h2tof2(v.y), f2 = h2tof2(v.z), f3 = h2tof2(v.w);
        acc[0] += f0.x; acc[1] += f0.y; acc[2] += f1.x; acc[3] += f1.y;
        acc[4] += f2.x; acc[5] += f2.y; acc[6] += f3.x; acc[7] += f3.y;
    }
    float di = g_dinv[n];
    float4 bb0 = *(const float4*)(b2 + j * 8);
    float4 bb1 = *(const float4*)(b2 + j * 8 + 4);
    float* op = out + (size_t)n * NCLS + j * 8;
    *(float4*)(op)     = make_float4(fmaf(acc[0], di, bb0.x), fmaf(acc[1], di, bb0.y),
                                     fmaf(acc[2], di, bb0.z), fmaf(acc[3], di, bb0.w));
    *(float4*)(op + 4) = make_float4(fmaf(acc[4], di, bb1.x), fmaf(acc[5], di, bb1.y),
                                     fmaf(acc[6], di, bb1.z), fmaf(acc[7], di, bb1.w));
}

// ---------------- launch ----------------
extern "C" void kernel_launch(void* const* d_in, const int* in_sizes, int n_in,
                              void* d_out, int out_size) {
    const float* x   = (const float*)d_in[0];
    const int*   ei  = (const int*)d_in[1];
    const float* W1  = (const float*)d_in[2];
    const float* b1  = (const float*)d_in[3];
    const float* W2  = (const float*)d_in[4];
    const float* b2  = (const float*)d_in[5];
    float* out = (float*)d_out;

    const int* src = ei;
    const int* dst = ei + NEDGES;

    // CSR build + dinv
    k_zero<<<(NNODES + 255) / 256, 256>>>();
    k_hist<<<(NEDGES + 255) / 256, 256>>>(dst);
    k_scan1<<<SCAN_BLOCKS, 1024>>>();
    k_scan2<<<1, 128>>>();
    k_fill<<<(NEDGES + 255) / 256, 256>>>(src, dst);

    // layer 1
    k_gemm1<<<(NNODES + 127) / 128, 128>>>(x, W1);
    k_agg1<<<(NNODES * 8 + 255) / 256, 256>>>(b1);

    // layer 2
    k_gemm2<<<(NNODES + 63) / 64, 256>>>(W2);
    k_agg2<<<(NNODES * 5 + 255) / 256, 256>>>(b2, out);
}